// round 14
// baseline (speedup 1.0000x reference)
#include <cuda_runtime.h>
#include <math.h>
#include <stdint.h>

#define NN 200000
#define KK 64
#define Q_MIN 0.1f
#define NT 256
#define NB1 148                 // pass1: exactly one wave, grid-stride over vec4
#define NV4 50000               // NN/4
#define NBP 391                 // pair-role blocks: 512 hits each (2/thread)
#define NBY 782                 // payload-role blocks: 256 hits each
#define NBTOT (NBP + NBY)

// ---------------- device globals (scratch; zero-initialized at load, self-reset each run) ----------------
__device__ unsigned long long g_key[KK];
__device__ float g_pwden[KK];
__device__ float g_noise_b;
__device__ int   g_noise_n;
__device__ float4 g_obj[KK];               // {x, y, qv*valid, 0}
__device__ float g_invpw[KK];              // valid / (pw_den + 1e-9)
__device__ float g_nvalid;
__device__ float g_beta_alpha;
__device__ float g_sumqv;
__device__ double g_acc[2];                // [0]=pair raw, [1]=payload raw
__device__ unsigned g_ctr1, g_ctr2;

// ---------------- helpers ----------------
__device__ __forceinline__ float clipb(float b) {
    return fminf(fmaxf(b, 1e-6f), 1.0f - 1e-6f);
}
__device__ __forceinline__ float huberf(float x, float d) {
    float ax = fabsf(x);
    return (ax < d) ? x * x : (d * d + 2.0f * d * (ax - d));
}
__device__ __forceinline__ float softclipf(float x, float s) {
    float y = x / s;
    y = (y > 1.0f) ? __logf(y + 1.0f) : y;
    return y * s;
}
__device__ __forceinline__ float sqrt_approx(float x) {
    float r;
    asm("sqrt.approx.f32 %0, %1;" : "=f"(r) : "f"(x));
    return r;
}
__device__ __forceinline__ float atanh_sq_q(float b) {
    float a = 0.5f * __logf(__fdividef(1.0f + b, 1.0f - b));
    return fmaf(a, a, Q_MIN);
}

// ---------------- kernel 1: per-object argmax / sums + noise + alpha extract (one wave, grid-stride) ----------------
__global__ void __launch_bounds__(NT)
k_pass1(const float4* __restrict__ beta4, const int4* __restrict__ tidx4,
        const float* __restrict__ beta, const float* __restrict__ cc) {
    __shared__ unsigned long long s_key[KK];
    __shared__ float s_pw[KK];
    __shared__ float s_nb[8];
    __shared__ int   s_nn[8];

    int t = threadIdx.x;
    if (t < KK) { s_key[t] = 0ull; s_pw[t] = 0.0f; }
    __syncthreads();

    float nb = 0.0f; int nn = 0;
    for (int vidx = blockIdx.x * NT + t; vidx < NV4; vidx += NB1 * NT) {
        float4 b4 = beta4[vidx];
        int4   k4 = tidx4[vidx];
        float bs[4] = {b4.x, b4.y, b4.z, b4.w};
        int    ks[4] = {k4.x, k4.y, k4.z, k4.w};
        int i0 = vidx * 4;
        #pragma unroll
        for (int u = 0; u < 4; u++) {
            int k = ks[u];
            float b = clipb(bs[u]);
            if (k > 0) {
                int o = k - 1;
                unsigned long long key =
                    ((unsigned long long)__float_as_uint(b) << 32) |
                    (unsigned long long)(0xFFFFFFFFu - (unsigned)(i0 + u));
                atomicMax(&s_key[o], key);
                atomicAdd(&s_pw[o], b);
            } else {
                nb += b; nn += 1;
            }
        }
    }
    #pragma unroll
    for (int off = 16; off; off >>= 1) {
        nb += __shfl_down_sync(0xffffffffu, nb, off);
        nn += __shfl_down_sync(0xffffffffu, nn, off);
    }
    int warp = t >> 5, lane = t & 31;
    if (lane == 0) { s_nb[warp] = nb; s_nn[warp] = nn; }
    __syncthreads();
    if (t == 0) {
        float tb = 0.0f; int tn = 0;
        #pragma unroll
        for (int w = 0; w < 8; w++) { tb += s_nb[w]; tn += s_nn[w]; }
        if (tn > 0) { atomicAdd(&g_noise_b, tb); atomicAdd(&g_noise_n, tn); }
    }
    if (t < KK && s_key[t] != 0ull) {
        atomicMax(&g_key[t], s_key[t]);
        atomicAdd(&g_pwden[t], s_pw[t]);
    }

    // ---- last-block-done: extract alpha info ----
    __shared__ int s_last;
    __shared__ float s_val[KK], s_bt[KK], s_qv[KK];
    __threadfence();
    if (t == 0) {
        unsigned c = atomicAdd(&g_ctr1, 1u);
        s_last = (c == NB1 - 1) ? 1 : 0;
    }
    __syncthreads();
    if (s_last) {
        __threadfence();
        if (t < KK) {
            unsigned long long key = g_key[t];
            float valid = (key != 0ull) ? 1.0f : 0.0f;
            unsigned ia = (key != 0ull)
                ? (0xFFFFFFFFu - (unsigned)(key & 0xFFFFFFFFull)) : 0u;
            float b = clipb(beta[ia]);
            float qv = atanh_sq_q(b) * valid;
            g_obj[t] = make_float4(cc[2 * ia], cc[2 * ia + 1], qv, 0.0f);
            g_invpw[t] = valid / (g_pwden[t] + 1e-9f);
            s_val[t] = valid;
            s_bt[t]  = (1.0f - b) * valid;
            s_qv[t]  = qv;
        }
        __syncthreads();
        if (t == 0) {
            float v = 0.0f, bt = 0.0f, sq = 0.0f;
            #pragma unroll
            for (int k = 0; k < KK; k++) { v += s_val[k]; bt += s_bt[k]; sq += s_qv[k]; }
            g_nvalid = fmaxf(v, 1.0f);
            g_beta_alpha = bt;
            g_sumqv = sq;
        }
    }
}

// ---------------- kernel 2: fused worker, NT=256 ----------------
// blocks [0, NBP): pair role, 512 hits/block (2 per thread, shared LDS stream)
// blocks [NBP, NBTOT): payload role, 256 hits/block
__global__ void __launch_bounds__(NT)
k_work(const float* __restrict__ beta, const float2* __restrict__ cc,
       const float* __restrict__ pred_e, const float2* __restrict__ pred_p,
       const float* __restrict__ pred_t, const float2* __restrict__ pred_id,
       const float* __restrict__ t_e, const float2* __restrict__ t_p,
       const float* __restrict__ t_t, const int* __restrict__ tidx,
       float* __restrict__ out) {
    int t = threadIdx.x;
    int bid = blockIdx.x;
    bool isPair = (bid < NBP);

    float acc = 0.0f;
    __shared__ float4 sobj[KK];     // pair: {x,y,qv}; payload: reused as sinv

    if (isPair) {
        if (t < KK) sobj[t] = g_obj[t];
        __syncthreads();

        int i0 = bid * (2 * NT) + t;
        int i1 = i0 + NT;
        bool v0 = (i0 < NN);
        bool v1 = (i1 < NN);
        int j0 = v0 ? i0 : 0;
        int j1 = v1 ? i1 : 0;

        int myk0 = v0 ? (tidx[j0] - 1) : -1;
        int myk1 = v1 ? (tidx[j1] - 1) : -1;
        float b0 = clipb(beta[j0]);
        float b1 = clipb(beta[j1]);
        float2 c0 = cc[j0];
        float2 c1 = cc[j1];
        float q0 = v0 ? atanh_sq_q(b0) : 0.0f;
        float q1 = v1 ? atanh_sq_q(b1) : 0.0f;

        // a = sum_k qv_k * min(d,1); rep = sumQV - a (includes self)
        float a0 = 0.0f, a1 = 0.0f;
        #pragma unroll
        for (int k = 0; k < KK; k++) {
            float4 o = sobj[k];
            float dx0 = c0.x - o.x, dy0 = c0.y - o.y;
            float dx1 = c1.x - o.x, dy1 = c1.y - o.y;
            float d20 = fmaf(dx0, dx0, fmaf(dy0, dy0, 1e-9f));
            float d21 = fmaf(dx1, dx1, fmaf(dy1, dy1, 1e-9f));
            float d0 = sqrt_approx(d20);
            float d1 = sqrt_approx(d21);
            a0 = fmaf(o.z, fminf(d0, 1.0f), a0);
            a1 = fmaf(o.z, fminf(d1, 1.0f), a1);
        }
        float sq = g_sumqv;
        float rep0 = sq - a0;
        float rep1 = sq - a1;

        if (myk0 >= 0) {
            float4 o = sobj[myk0];
            float dx = c0.x - o.x, dy = c0.y - o.y;
            float d2 = fmaf(dx, dx, dy * dy);
            float d  = sqrt_approx(d2 + 1e-9f);
            float r  = fmaxf(1.0f - d, 0.0f);
            acc = q0 * (rep0 - o.z * r + o.z * d2);
        } else {
            acc = q0 * rep0;
        }
        if (myk1 >= 0) {
            float4 o = sobj[myk1];
            float dx = c1.x - o.x, dy = c1.y - o.y;
            float d2 = fmaf(dx, dx, dy * dy);
            float d  = sqrt_approx(d2 + 1e-9f);
            float r  = fmaxf(1.0f - d, 0.0f);
            acc += q1 * (rep1 - o.z * r + o.z * d2);
        } else {
            acc += q1 * rep1;
        }
    } else {
        float* sinv = (float*)sobj;
        if (t < KK) sinv[t] = g_invpw[t];
        __syncthreads();

        int i = (bid - NBP) * NT + t;
        bool v = (i < NN);
        int j = v ? i : 0;

        int myk = v ? (tidx[j] - 1) : -1;
        if (myk >= 0) {
            float te = t_e[j];
            float we = (te > 10.0f) ? 1.0f : fmaxf((te - 0.5f) * (1.0f / 9.5f), 0.0f);
            if (we > 0.0f) {
                float b  = clipb(beta[j]);
                float pe = pred_e[j];
                float2 tp = t_p[j], pp = pred_p[j];
                float tt = t_t[j], pt = pred_t[j];
                float2 id0 = pred_id[3 * j];
                float2 id1 = pred_id[3 * j + 1];
                float2 id2 = pred_id[3 * j + 2];

                float de = te - pe;
                float el = softclipf(de * de / (te + 1.0f), 10.0f);

                float dpx = tp.x - pp.x, dpy = tp.y - pp.y;
                float dp2 = fmaf(dpx, dpx, dpy * dpy);
                float arg = sqrt_approx(fmaf(dp2, 0.01f, 0.01f));
                float pl  = softclipf(huberf(arg, 10.0f), 3.0f);

                float dt = tt - pt;
                float tl = softclipf(huberf(dt, 2.0f), 6.0f);

                float cl = (id0.x * id0.x + id0.y * id0.y +
                            id1.x * id1.x + id1.y * id1.y +
                            id2.x * id2.x + id2.y * id2.y) * (1e-8f / 6.0f);

                acc = b * we * sinv[myk] * (el + pl + tl + cl);
            }
        }
    }

    // block reduce (8 warps)
    #pragma unroll
    for (int off = 16; off; off >>= 1)
        acc += __shfl_down_sync(0xffffffffu, acc, off);
    __shared__ float sred[8];
    int warp = t >> 5, lane = t & 31;
    if (lane == 0) sred[warp] = acc;
    __syncthreads();
    if (t == 0) {
        float s = 0.0f;
        #pragma unroll
        for (int w = 0; w < 8; w++) s += sred[w];
        atomicAdd(&g_acc[isPair ? 0 : 1], (double)s);
    }

    // ---- last-block-done over the WHOLE fused grid: finalize + reset ----
    __shared__ int s_last;
    __threadfence();
    if (t == 0) {
        unsigned cnum = atomicAdd(&g_ctr2, 1u);
        s_last = (cnum == NBTOT - 1) ? 1 : 0;
    }
    __syncthreads();
    if (s_last) {                 // block-uniform: __syncthreads legal
        __threadfence();
        if (t == 0) {
            double nv = (double)g_nvalid;
            double noise_den = (g_noise_n > 0) ? (double)g_noise_n : 1.0;
            double L = g_acc[0] / ((double)NN * nv)
                     + (double)g_beta_alpha / nv
                     + (double)g_noise_b / noise_den
                     + g_acc[1] / nv;
            out[0] = (float)L;
        }
        __syncthreads();          // finalize reads complete before reset writes
        if (t < KK) { g_key[t] = 0ull; g_pwden[t] = 0.0f; }
        if (t == NT - 1) {
            g_noise_b = 0.0f; g_noise_n = 0;
            g_acc[0] = 0.0; g_acc[1] = 0.0;
            g_ctr1 = 0; g_ctr2 = 0;
        }
    }
}

// ---------------- launch ----------------
extern "C" void kernel_launch(void* const* d_in, const int* in_sizes, int n_in,
                              void* d_out, int out_size) {
    const float*  beta   = (const float*)d_in[0];
    const float*  cc     = (const float*)d_in[1];
    const float*  pred_e = (const float*)d_in[2];
    const float*  pred_p = (const float*)d_in[3];
    const float*  pred_t = (const float*)d_in[4];
    const float*  pred_i = (const float*)d_in[5];
    const float*  t_e    = (const float*)d_in[6];
    const float*  t_p    = (const float*)d_in[7];
    const float*  t_t    = (const float*)d_in[8];
    const int*    t_idx  = (const int*)d_in[9];
    float* out = (float*)d_out;

    k_pass1<<<NB1, NT>>>((const float4*)beta, (const int4*)t_idx, beta, cc);
    k_work<<<NBTOT, NT>>>(beta, (const float2*)cc, pred_e, (const float2*)pred_p,
                          pred_t, (const float2*)pred_i, t_e, (const float2*)t_p,
                          t_t, t_idx, out);
}

// round 16
// speedup vs baseline: 1.1750x; 1.1750x over previous
#include <cuda_runtime.h>
#include <math.h>
#include <stdint.h>

#define NN 200000
#define KK 64
#define Q_MIN 0.1f
#define NT 256
#define NB1 196                 // pass1: 4 items/thread (196*256*4 = 200704 >= NN)
#define NBP 391                 // pair-role blocks: 512 hits each (2/thread)
#define NBY 782                 // payload-role blocks: 256 hits each
#define NBTOT (NBP + NBY)

// ---------------- device globals (scratch; zero-initialized at load, self-reset each run) ----------------
__device__ unsigned long long g_key[KK];
__device__ float g_pwden[KK];
__device__ float g_noise_b;
__device__ int   g_noise_n;
__device__ float4 g_obj[KK];               // {x, y, qv*valid, 0}
__device__ float g_invpw[KK];              // valid / (pw_den + 1e-9)
__device__ float g_nvalid;
__device__ float g_beta_alpha;
__device__ float g_sumqv;
__device__ double g_acc[2];                // [0]=pair raw, [1]=payload raw
__device__ unsigned g_ctr1, g_ctr2;

// ---------------- helpers ----------------
__device__ __forceinline__ float clipb(float b) {
    return fminf(fmaxf(b, 1e-6f), 1.0f - 1e-6f);
}
__device__ __forceinline__ float huberf(float x, float d) {
    float ax = fabsf(x);
    return (ax < d) ? x * x : (d * d + 2.0f * d * (ax - d));
}
__device__ __forceinline__ float softclipf(float x, float s) {
    float y = x / s;
    y = (y > 1.0f) ? __logf(y + 1.0f) : y;
    return y * s;
}
__device__ __forceinline__ float sqrt_approx(float x) {
    float r;
    asm("sqrt.approx.f32 %0, %1;" : "=f"(r) : "f"(x));
    return r;
}
__device__ __forceinline__ float atanh_sq_q(float b) {
    float a = 0.5f * __logf(__fdividef(1.0f + b, 1.0f - b));
    return fmaf(a, a, Q_MIN);
}

// ---------------- kernel 1: per-object argmax / sums + noise + alpha extract (4 items/thread) ----------------
__global__ void __launch_bounds__(NT)
k_pass1(const float4* __restrict__ beta4, const int4* __restrict__ tidx4,
        const float* __restrict__ beta, const float* __restrict__ cc) {
    __shared__ unsigned long long s_key[KK];
    __shared__ float s_pw[KK];
    __shared__ float s_nb[8];
    __shared__ int   s_nn[8];

    int t = threadIdx.x;
    if (t < KK) { s_key[t] = 0ull; s_pw[t] = 0.0f; }
    __syncthreads();

    int base = blockIdx.x * NT + t;        // vec4 index
    float nb = 0.0f; int nn = 0;
    if (base * 4 < NN) {
        float4 b4 = beta4[base];
        int4   k4 = tidx4[base];
        float bs[4] = {b4.x, b4.y, b4.z, b4.w};
        int    ks[4] = {k4.x, k4.y, k4.z, k4.w};
        int i0 = base * 4;
        #pragma unroll
        for (int u = 0; u < 4; u++) {
            int i = i0 + u;
            if (i < NN) {
                int k = ks[u];
                float b = clipb(bs[u]);
                if (k > 0) {
                    int o = k - 1;
                    unsigned long long key =
                        ((unsigned long long)__float_as_uint(b) << 32) |
                        (unsigned long long)(0xFFFFFFFFu - (unsigned)i);
                    atomicMax(&s_key[o], key);
                    atomicAdd(&s_pw[o], b);
                } else {
                    nb += b; nn += 1;
                }
            }
        }
    }
    #pragma unroll
    for (int off = 16; off; off >>= 1) {
        nb += __shfl_down_sync(0xffffffffu, nb, off);
        nn += __shfl_down_sync(0xffffffffu, nn, off);
    }
    int warp = t >> 5, lane = t & 31;
    if (lane == 0) { s_nb[warp] = nb; s_nn[warp] = nn; }
    __syncthreads();
    if (t == 0) {
        float tb = 0.0f; int tn = 0;
        #pragma unroll
        for (int w = 0; w < 8; w++) { tb += s_nb[w]; tn += s_nn[w]; }
        if (tn > 0) { atomicAdd(&g_noise_b, tb); atomicAdd(&g_noise_n, tn); }
    }
    if (t < KK && s_key[t] != 0ull) {
        atomicMax(&g_key[t], s_key[t]);
        atomicAdd(&g_pwden[t], s_pw[t]);
    }

    // ---- last-block-done: extract alpha info ----
    __shared__ int s_last;
    __shared__ float s_val[KK], s_bt[KK], s_qv[KK];
    __threadfence();
    if (t == 0) {
        unsigned c = atomicAdd(&g_ctr1, 1u);
        s_last = (c == NB1 - 1) ? 1 : 0;
    }
    __syncthreads();
    if (s_last) {
        __threadfence();
        if (t < KK) {
            unsigned long long key = g_key[t];
            float valid = (key != 0ull) ? 1.0f : 0.0f;
            unsigned ia = (key != 0ull)
                ? (0xFFFFFFFFu - (unsigned)(key & 0xFFFFFFFFull)) : 0u;
            float b = clipb(beta[ia]);
            float qv = atanh_sq_q(b) * valid;
            g_obj[t] = make_float4(cc[2 * ia], cc[2 * ia + 1], qv, 0.0f);
            g_invpw[t] = valid / (g_pwden[t] + 1e-9f);
            s_val[t] = valid;
            s_bt[t]  = (1.0f - b) * valid;
            s_qv[t]  = qv;
        }
        __syncthreads();
        if (t == 0) {
            float v = 0.0f, bt = 0.0f, sq = 0.0f;
            #pragma unroll
            for (int k = 0; k < KK; k++) { v += s_val[k]; bt += s_bt[k]; sq += s_qv[k]; }
            g_nvalid = fmaxf(v, 1.0f);
            g_beta_alpha = bt;
            g_sumqv = sq;
        }
    }
}

// ---------------- kernel 2: fused worker, NT=256 ----------------
// blocks [0, NBP): pair role, 512 hits/block (2 per thread, shared LDS stream)
// blocks [NBP, NBTOT): payload role, 256 hits/block
__global__ void __launch_bounds__(NT)
k_work(const float* __restrict__ beta, const float2* __restrict__ cc,
       const float* __restrict__ pred_e, const float2* __restrict__ pred_p,
       const float* __restrict__ pred_t, const float2* __restrict__ pred_id,
       const float* __restrict__ t_e, const float2* __restrict__ t_p,
       const float* __restrict__ t_t, const int* __restrict__ tidx,
       float* __restrict__ out) {
    int t = threadIdx.x;
    int bid = blockIdx.x;
    bool isPair = (bid < NBP);

    float acc = 0.0f;
    __shared__ float4 sobj[KK];     // pair: {x,y,qv}; payload: reused as sinv

    if (isPair) {
        if (t < KK) sobj[t] = g_obj[t];
        __syncthreads();

        int i0 = bid * (2 * NT) + t;
        int i1 = i0 + NT;
        bool v0 = (i0 < NN);
        bool v1 = (i1 < NN);
        int j0 = v0 ? i0 : 0;
        int j1 = v1 ? i1 : 0;

        int myk0 = v0 ? (tidx[j0] - 1) : -1;
        int myk1 = v1 ? (tidx[j1] - 1) : -1;
        float b0 = clipb(beta[j0]);
        float b1 = clipb(beta[j1]);
        float2 c0 = cc[j0];
        float2 c1 = cc[j1];
        float q0 = v0 ? atanh_sq_q(b0) : 0.0f;
        float q1 = v1 ? atanh_sq_q(b1) : 0.0f;

        // a = sum_k qv_k * min(d,1); rep = sumQV - a (includes self)
        float a0 = 0.0f, a1 = 0.0f;
        #pragma unroll
        for (int k = 0; k < KK; k++) {
            float4 o = sobj[k];
            float dx0 = c0.x - o.x, dy0 = c0.y - o.y;
            float dx1 = c1.x - o.x, dy1 = c1.y - o.y;
            float d20 = fmaf(dx0, dx0, fmaf(dy0, dy0, 1e-9f));
            float d21 = fmaf(dx1, dx1, fmaf(dy1, dy1, 1e-9f));
            float d0 = sqrt_approx(d20);
            float d1 = sqrt_approx(d21);
            a0 = fmaf(o.z, fminf(d0, 1.0f), a0);
            a1 = fmaf(o.z, fminf(d1, 1.0f), a1);
        }
        float sq = g_sumqv;
        float rep0 = sq - a0;
        float rep1 = sq - a1;

        if (myk0 >= 0) {
            float4 o = sobj[myk0];
            float dx = c0.x - o.x, dy = c0.y - o.y;
            float d2 = fmaf(dx, dx, dy * dy);
            float d  = sqrt_approx(d2 + 1e-9f);
            float r  = fmaxf(1.0f - d, 0.0f);
            acc = q0 * (rep0 - o.z * r + o.z * d2);
        } else {
            acc = q0 * rep0;
        }
        if (myk1 >= 0) {
            float4 o = sobj[myk1];
            float dx = c1.x - o.x, dy = c1.y - o.y;
            float d2 = fmaf(dx, dx, dy * dy);
            float d  = sqrt_approx(d2 + 1e-9f);
            float r  = fmaxf(1.0f - d, 0.0f);
            acc += q1 * (rep1 - o.z * r + o.z * d2);
        } else {
            acc += q1 * rep1;
        }
    } else {
        float* sinv = (float*)sobj;
        if (t < KK) sinv[t] = g_invpw[t];
        __syncthreads();

        int i = (bid - NBP) * NT + t;
        bool v = (i < NN);
        int j = v ? i : 0;

        int myk = v ? (tidx[j] - 1) : -1;
        if (myk >= 0) {
            float te = t_e[j];
            float we = (te > 10.0f) ? 1.0f : fmaxf((te - 0.5f) * (1.0f / 9.5f), 0.0f);
            if (we > 0.0f) {
                float b  = clipb(beta[j]);
                float pe = pred_e[j];
                float2 tp = t_p[j], pp = pred_p[j];
                float tt = t_t[j], pt = pred_t[j];
                float2 id0 = pred_id[3 * j];
                float2 id1 = pred_id[3 * j + 1];
                float2 id2 = pred_id[3 * j + 2];

                float de = te - pe;
                float el = softclipf(de * de / (te + 1.0f), 10.0f);

                float dpx = tp.x - pp.x, dpy = tp.y - pp.y;
                float dp2 = fmaf(dpx, dpx, dpy * dpy);
                float arg = sqrt_approx(fmaf(dp2, 0.01f, 0.01f));
                float pl  = softclipf(huberf(arg, 10.0f), 3.0f);

                float dt = tt - pt;
                float tl = softclipf(huberf(dt, 2.0f), 6.0f);

                float cl = (id0.x * id0.x + id0.y * id0.y +
                            id1.x * id1.x + id1.y * id1.y +
                            id2.x * id2.x + id2.y * id2.y) * (1e-8f / 6.0f);

                acc = b * we * sinv[myk] * (el + pl + tl + cl);
            }
        }
    }

    // block reduce (8 warps)
    #pragma unroll
    for (int off = 16; off; off >>= 1)
        acc += __shfl_down_sync(0xffffffffu, acc, off);
    __shared__ float sred[8];
    int warp = t >> 5, lane = t & 31;
    if (lane == 0) sred[warp] = acc;
    __syncthreads();
    if (t == 0) {
        float s = 0.0f;
        #pragma unroll
        for (int w = 0; w < 8; w++) s += sred[w];
        atomicAdd(&g_acc[isPair ? 0 : 1], (double)s);
    }

    // ---- last-block-done over the WHOLE fused grid: finalize + reset ----
    __shared__ int s_last;
    __threadfence();
    if (t == 0) {
        unsigned cnum = atomicAdd(&g_ctr2, 1u);
        s_last = (cnum == NBTOT - 1) ? 1 : 0;
    }
    __syncthreads();
    if (s_last) {                 // block-uniform: __syncthreads legal
        __threadfence();
        if (t == 0) {
            double nv = (double)g_nvalid;
            double noise_den = (g_noise_n > 0) ? (double)g_noise_n : 1.0;
            double L = g_acc[0] / ((double)NN * nv)
                     + (double)g_beta_alpha / nv
                     + (double)g_noise_b / noise_den
                     + g_acc[1] / nv;
            out[0] = (float)L;
        }
        __syncthreads();          // finalize reads complete before reset writes
        if (t < KK) { g_key[t] = 0ull; g_pwden[t] = 0.0f; }
        if (t == NT - 1) {
            g_noise_b = 0.0f; g_noise_n = 0;
            g_acc[0] = 0.0; g_acc[1] = 0.0;
            g_ctr1 = 0; g_ctr2 = 0;
        }
    }
}

// ---------------- launch ----------------
extern "C" void kernel_launch(void* const* d_in, const int* in_sizes, int n_in,
                              void* d_out, int out_size) {
    const float*  beta   = (const float*)d_in[0];
    const float*  cc     = (const float*)d_in[1];
    const float*  pred_e = (const float*)d_in[2];
    const float*  pred_p = (const float*)d_in[3];
    const float*  pred_t = (const float*)d_in[4];
    const float*  pred_i = (const float*)d_in[5];
    const float*  t_e    = (const float*)d_in[6];
    const float*  t_p    = (const float*)d_in[7];
    const float*  t_t    = (const float*)d_in[8];
    const int*    t_idx  = (const int*)d_in[9];
    float* out = (float*)d_out;

    k_pass1<<<NB1, NT>>>((const float4*)beta, (const int4*)t_idx, beta, cc);
    k_work<<<NBTOT, NT>>>(beta, (const float2*)cc, pred_e, (const float2*)pred_p,
                          pred_t, (const float2*)pred_i, t_e, (const float2*)t_p,
                          t_t, t_idx, out);
}